// round 10
// baseline (speedup 1.0000x reference)
#include <cuda_runtime.h>
#include <cstdint>

#define KBINS 16
#define MAGIC 8388608.0f      // 2^23
#define TPB 256
#define SI 3                  // input ring stages
#define SO 2                  // output ring stages
#define TILE_ELEMS 2048       // 8KB per tile
#define TILE_BYTES (TILE_ELEMS * 4)

// ---- mbarrier / bulk-async helpers ----------------------------------------
__device__ __forceinline__ uint32_t smem_u32(const void* p) {
    return (uint32_t)__cvta_generic_to_shared(p);
}
__device__ __forceinline__ void mbar_init(uint32_t a, uint32_t cnt) {
    asm volatile("mbarrier.init.shared.b64 [%0], %1;" :: "r"(a), "r"(cnt) : "memory");
}
__device__ __forceinline__ void mbar_expect_tx(uint32_t a, uint32_t bytes) {
    asm volatile("mbarrier.arrive.expect_tx.shared.b64 _, [%0], %1;"
                 :: "r"(a), "r"(bytes) : "memory");
}
__device__ __forceinline__ void mbar_wait(uint32_t a, uint32_t ph) {
    uint32_t done;
    asm volatile("{\n\t.reg .pred p;\n\t"
                 "mbarrier.try_wait.parity.acquire.cta.shared::cta.b64 p, [%1], %2;\n\t"
                 "selp.b32 %0, 1, 0, p;\n\t}"
                 : "=r"(done) : "r"(a), "r"(ph) : "memory");
    while (!done) {
        asm volatile("{\n\t.reg .pred p;\n\t"
                     "mbarrier.try_wait.parity.acquire.cta.shared::cta.b64 p, [%1], %2, 0x989680;\n\t"
                     "selp.b32 %0, 1, 0, p;\n\t}"
                     : "=r"(done) : "r"(a), "r"(ph) : "memory");
    }
}
__device__ __forceinline__ void bulk_g2s(uint32_t dst, const void* src,
                                         uint32_t bytes, uint32_t mbar) {
    asm volatile("cp.async.bulk.shared::cluster.global.mbarrier::complete_tx::bytes "
                 "[%0], [%1], %2, [%3];"
                 :: "r"(dst), "l"(src), "r"(bytes), "r"(mbar) : "memory");
}
__device__ __forceinline__ void bulk_s2g(void* gdst, uint32_t ssrc, uint32_t bytes) {
    asm volatile("cp.async.bulk.global.shared::cta.bulk_group [%0], [%1], %2;"
                 :: "l"(gdst), "r"(ssrc), "r"(bytes) : "memory");
}
__device__ __forceinline__ void bulk_commit() {
    asm volatile("cp.async.bulk.commit_group;" ::: "memory");
}
template <int N>
__device__ __forceinline__ void bulk_wait() {
    asm volatile("cp.async.bulk.wait_group %0;" :: "n"(N) : "memory");
}
__device__ __forceinline__ void fence_async_smem() {
    asm volatile("fence.proxy.async.shared::cta;" ::: "memory");
}

// ---- LCQ per-element math (bit-exact magic-number rounding) ----------------
__device__ __forceinline__ float lcq_elem(float xx, float c,
                                          const float2* __restrict__ tab,
                                          const float* __restrict__ lutA) {
    float f = fminf(fabsf(xx) * c, 15.9999990f);
    int bi = __float_as_int(__fadd_rd(f, MAGIC)) & 15;   // floor(f)
    float2 gd = tab[bi];                                 // {gx, d}
    float y15 = fmaf(gd.x, f, gd.y);
    int q = __float_as_int(__fadd_rn(y15, MAGIC)) & 15;  // rint(y15)
    return copysignf(lutA[q], xx);
}
__device__ __forceinline__ void lcq_vec4(float4& v, float c,
                                         const float2* __restrict__ tab,
                                         const float* __restrict__ lutA) {
    v.x = lcq_elem(v.x, c, tab, lutA);
    v.y = lcq_elem(v.y, c, tab, lutA);
    v.z = lcq_elem(v.z, c, tab, lutA);
    v.w = lcq_elem(v.w, c, tab, lutA);
}

__global__ void __launch_bounds__(TPB)
lcq_kernel(const float* __restrict__ x,
           const float* __restrict__ thr,
           const float* __restrict__ theta,
           const float* __restrict__ dst,
           const int* __restrict__ qp,
           float* __restrict__ out,
           int ntiles, int n) {
    __shared__ __align__(128) float s_in[SI][TILE_ELEMS];   // 24KB
    __shared__ __align__(128) float s_out[SO][TILE_ELEMS];  // 16KB
    __shared__ uint64_t s_full[SI];
    __shared__ float2 s_tab[KBINS];
    __shared__ float  s_lutA[KBINS];
    __shared__ float  s_c;

    const int tid = threadIdx.x;

    if (tid == 0) {
        // constant tables: softmax/cumsum/affine folds + expand LUT
        float th[KBINS];
        float m = theta[0];
        #pragma unroll
        for (int i = 0; i < KBINS; i++) { th[i] = theta[i]; m = fmaxf(m, th[i]); }
        float sum = 0.0f;
        #pragma unroll
        for (int i = 0; i < KBINS; i++) { th[i] = expf(th[i] - m); sum += th[i]; }
        float inv = 1.0f / sum;
        float gamma[KBINS], beta[KBINS];
        float acc = 0.0f;
        #pragma unroll
        for (int i = 0; i < KBINS; i++) {
            float t = th[i] * inv;
            gamma[i] = t * (float)KBINS;
            beta[i]  = acc;
            acc += t;
        }
        float s = (float)qp[0];
        float alpha = thr[0];
        #pragma unroll
        for (int i = 0; i < KBINS; i++) {
            float gx = s * gamma[i] * 0.0625f;
            s_tab[i] = make_float2(gx, fmaf(-gx, (float)i, s * beta[i]));
        }
        #pragma unroll
        for (int q = 0; q < KBINS; q++) {
            float t = (float)q / s;
            int idx = 0;
            #pragma unroll
            for (int j = 0; j < KBINS; j++)
                if (beta[j] <= t) idx = j;
            s_lutA[q] = alpha * ((t - beta[idx]) / gamma[idx] + dst[idx]);
        }
        s_c = 16.0f / alpha;

        #pragma unroll
        for (int sg = 0; sg < SI; sg++)
            mbar_init(smem_u32(&s_full[sg]), 1);
    }
    __syncthreads();

    const float c = s_c;

    int my_count = 0;
    if (blockIdx.x < ntiles)
        my_count = (ntiles - blockIdx.x + gridDim.x - 1) / gridDim.x;

    // ---- prologue: fill input ring ----
    if (tid == 0) {
        int pre = my_count < SI ? my_count : SI;
        for (int k = 0; k < pre; k++) {
            long long t = blockIdx.x + (long long)k * gridDim.x;
            uint32_t mb = smem_u32(&s_full[k]);
            mbar_expect_tx(mb, TILE_BYTES);
            bulk_g2s(smem_u32(&s_in[k][0]), x + t * TILE_ELEMS, TILE_BYTES, mb);
        }
    }

    // ---- steady state ----
    int si = 0, ph = 0, so = 0;
    for (int k = 0; k < my_count; k++) {
        long long t = blockIdx.x + (long long)k * gridDim.x;

        mbar_wait(smem_u32(&s_full[si]), ph);

        const float4* bin = (const float4*)&s_in[si][0];
        float4 v0 = bin[tid];
        float4 v1 = bin[tid + TPB];
        lcq_vec4(v0, c, s_tab, s_lutA);
        lcq_vec4(v1, c, s_tab, s_lutA);

        // output slot `so` must be free (its store SO iterations ago done)
        if (tid == 0) bulk_wait<SO - 1>();
        __syncthreads();   // all reads of s_in[si] done + out slot free

        // recycle input stage immediately
        if (tid == 0 && k + SI < my_count) {
            long long tn = blockIdx.x + (long long)(k + SI) * gridDim.x;
            uint32_t mb = smem_u32(&s_full[si]);
            mbar_expect_tx(mb, TILE_BYTES);
            bulk_g2s(smem_u32(&s_in[si][0]), x + tn * TILE_ELEMS, TILE_BYTES, mb);
        }

        float4* bout = (float4*)&s_out[so][0];
        bout[tid] = v0;
        bout[tid + TPB] = v1;
        __syncthreads();   // STS visible CTA-wide

        if (tid == 0) {
            fence_async_smem();   // order generic STS before async-proxy read
            bulk_s2g(out + t * TILE_ELEMS, smem_u32(&s_out[so][0]), TILE_BYTES);
            bulk_commit();
        }

        if (++si == SI) { si = 0; ph ^= 1; }
        if (++so == SO) so = 0;
    }

    if (tid == 0 && my_count > 0) bulk_wait<0>();   // drain stores

    // ---- remainder elements (n not multiple of TILE_ELEMS) ----
    if (blockIdx.x == gridDim.x - 1) {
        for (long long i = (long long)ntiles * TILE_ELEMS + tid; i < n; i += TPB)
            out[i] = lcq_elem(__ldcs(&x[i]), c, s_tab, s_lutA);
    }
}

extern "C" void kernel_launch(void* const* d_in, const int* in_sizes, int n_in,
                              void* d_out, int out_size) {
    // metadata order: x, threshold, theta, dst, Qn, Qp, num_elements
    const float* x     = (const float*)d_in[0];
    const float* thr   = (const float*)d_in[1];
    const float* theta = (const float*)d_in[2];
    const float* dst   = (const float*)d_in[3];
    const int*   qp    = (const int*)d_in[5];
    float* out = (float*)d_out;

    int n = in_sizes[0];
    int ntiles = n / TILE_ELEMS;

    int blocks = 148 * 3;               // 3 CTAs/SM (40KB smem each)
    if (blocks > ntiles) blocks = ntiles;
    if (blocks < 1) blocks = 1;

    lcq_kernel<<<blocks, TPB>>>(x, thr, theta, dst, qp, out, ntiles, n);
}

// round 11
// speedup vs baseline: 1.0612x; 1.0612x over previous
#include <cuda_runtime.h>
#include <cstdint>

#define KBINS 16
#define MAGIC 8388608.0f      // 2^23
#define TPB 256
#define SI 3                  // input ring stages
#define SO 2                  // output ring stages
#define TILE_ELEMS 2048       // 8KB per tile
#define TILE_BYTES (TILE_ELEMS * 4)

// ---- mbarrier / bulk-async helpers ----------------------------------------
__device__ __forceinline__ uint32_t smem_u32(const void* p) {
    return (uint32_t)__cvta_generic_to_shared(p);
}
__device__ __forceinline__ void mbar_init(uint32_t a, uint32_t cnt) {
    asm volatile("mbarrier.init.shared.b64 [%0], %1;" :: "r"(a), "r"(cnt) : "memory");
}
__device__ __forceinline__ void mbar_expect_tx(uint32_t a, uint32_t bytes) {
    asm volatile("mbarrier.arrive.expect_tx.shared.b64 _, [%0], %1;"
                 :: "r"(a), "r"(bytes) : "memory");
}
__device__ __forceinline__ void mbar_wait(uint32_t a, uint32_t ph) {
    uint32_t done;
    asm volatile("{\n\t.reg .pred p;\n\t"
                 "mbarrier.try_wait.parity.acquire.cta.shared::cta.b64 p, [%1], %2;\n\t"
                 "selp.b32 %0, 1, 0, p;\n\t}"
                 : "=r"(done) : "r"(a), "r"(ph) : "memory");
    while (!done) {
        asm volatile("{\n\t.reg .pred p;\n\t"
                     "mbarrier.try_wait.parity.acquire.cta.shared::cta.b64 p, [%1], %2, 0x989680;\n\t"
                     "selp.b32 %0, 1, 0, p;\n\t}"
                     : "=r"(done) : "r"(a), "r"(ph) : "memory");
    }
}
__device__ __forceinline__ uint64_t l2_evict_first_policy() {
    uint64_t pol;
    asm("createpolicy.fractional.L2::evict_first.b64 %0, 1.0;" : "=l"(pol));
    return pol;
}
__device__ __forceinline__ void bulk_g2s(uint32_t dst, const void* src,
                                         uint32_t bytes, uint32_t mbar,
                                         uint64_t pol) {
    asm volatile("cp.async.bulk.shared::cluster.global.mbarrier::complete_tx::bytes"
                 ".L2::cache_hint [%0], [%1], %2, [%3], %4;"
                 :: "r"(dst), "l"(src), "r"(bytes), "r"(mbar), "l"(pol) : "memory");
}
__device__ __forceinline__ void bulk_s2g(void* gdst, uint32_t ssrc, uint32_t bytes,
                                         uint64_t pol) {
    asm volatile("cp.async.bulk.global.shared::cta.bulk_group"
                 ".L2::cache_hint [%0], [%1], %2, %3;"
                 :: "l"(gdst), "r"(ssrc), "r"(bytes), "l"(pol) : "memory");
}
__device__ __forceinline__ void bulk_commit() {
    asm volatile("cp.async.bulk.commit_group;" ::: "memory");
}
template <int N>
__device__ __forceinline__ void bulk_wait() {
    asm volatile("cp.async.bulk.wait_group %0;" :: "n"(N) : "memory");
}
__device__ __forceinline__ void fence_async_smem() {
    asm volatile("fence.proxy.async.shared::cta;" ::: "memory");
}

// ---- LCQ per-element math (bit-exact magic-number rounding) ----------------
__device__ __forceinline__ float lcq_elem(float xx, float c,
                                          const float2* __restrict__ tab,
                                          const float* __restrict__ lutA) {
    float f = fminf(fabsf(xx) * c, 15.9999990f);
    int bi = __float_as_int(__fadd_rd(f, MAGIC)) & 15;   // floor(f)
    float2 gd = tab[bi];                                 // {gx, d}
    float y15 = fmaf(gd.x, f, gd.y);
    int q = __float_as_int(__fadd_rn(y15, MAGIC)) & 15;  // rint(y15)
    return copysignf(lutA[q], xx);
}
__device__ __forceinline__ void lcq_vec4(float4& v, float c,
                                         const float2* __restrict__ tab,
                                         const float* __restrict__ lutA) {
    v.x = lcq_elem(v.x, c, tab, lutA);
    v.y = lcq_elem(v.y, c, tab, lutA);
    v.z = lcq_elem(v.z, c, tab, lutA);
    v.w = lcq_elem(v.w, c, tab, lutA);
}

__global__ void __launch_bounds__(TPB)
lcq_kernel(const float* __restrict__ x,
           const float* __restrict__ thr,
           const float* __restrict__ theta,
           const float* __restrict__ dst,
           const int* __restrict__ qp,
           float* __restrict__ out,
           int ntiles, int n) {
    __shared__ __align__(128) float s_in[SI][TILE_ELEMS];   // 24KB
    __shared__ __align__(128) float s_out[SO][TILE_ELEMS];  // 16KB
    __shared__ uint64_t s_full[SI];
    __shared__ float2 s_tab[KBINS];
    __shared__ float  s_lutA[KBINS];
    __shared__ float  s_c;

    const int tid = threadIdx.x;
    const uint64_t pol = l2_evict_first_policy();

    if (tid == 0) {
        // constant tables: softmax/cumsum/affine folds + expand LUT
        float th[KBINS];
        float m = theta[0];
        #pragma unroll
        for (int i = 0; i < KBINS; i++) { th[i] = theta[i]; m = fmaxf(m, th[i]); }
        float sum = 0.0f;
        #pragma unroll
        for (int i = 0; i < KBINS; i++) { th[i] = expf(th[i] - m); sum += th[i]; }
        float inv = 1.0f / sum;
        float gamma[KBINS], beta[KBINS];
        float acc = 0.0f;
        #pragma unroll
        for (int i = 0; i < KBINS; i++) {
            float t = th[i] * inv;
            gamma[i] = t * (float)KBINS;
            beta[i]  = acc;
            acc += t;
        }
        float s = (float)qp[0];
        float alpha = thr[0];
        #pragma unroll
        for (int i = 0; i < KBINS; i++) {
            float gx = s * gamma[i] * 0.0625f;
            s_tab[i] = make_float2(gx, fmaf(-gx, (float)i, s * beta[i]));
        }
        #pragma unroll
        for (int q = 0; q < KBINS; q++) {
            float t = (float)q / s;
            int idx = 0;
            #pragma unroll
            for (int j = 0; j < KBINS; j++)
                if (beta[j] <= t) idx = j;
            s_lutA[q] = alpha * ((t - beta[idx]) / gamma[idx] + dst[idx]);
        }
        s_c = 16.0f / alpha;

        #pragma unroll
        for (int sg = 0; sg < SI; sg++)
            mbar_init(smem_u32(&s_full[sg]), 1);
    }
    __syncthreads();

    const float c = s_c;

    int my_count = 0;
    if (blockIdx.x < ntiles)
        my_count = (ntiles - blockIdx.x + gridDim.x - 1) / gridDim.x;

    // ---- prologue: fill input ring ----
    if (tid == 0) {
        int pre = my_count < SI ? my_count : SI;
        for (int k = 0; k < pre; k++) {
            long long t = blockIdx.x + (long long)k * gridDim.x;
            uint32_t mb = smem_u32(&s_full[k]);
            mbar_expect_tx(mb, TILE_BYTES);
            bulk_g2s(smem_u32(&s_in[k][0]), x + t * TILE_ELEMS, TILE_BYTES, mb, pol);
        }
    }

    // ---- steady state ----
    int si = 0, ph = 0, so = 0;
    for (int k = 0; k < my_count; k++) {
        long long t = blockIdx.x + (long long)k * gridDim.x;

        mbar_wait(smem_u32(&s_full[si]), ph);

        const float4* bin = (const float4*)&s_in[si][0];
        float4 v0 = bin[tid];
        float4 v1 = bin[tid + TPB];
        lcq_vec4(v0, c, s_tab, s_lutA);
        lcq_vec4(v1, c, s_tab, s_lutA);

        // output slot `so` must be free (its store SO iterations ago done)
        if (tid == 0) bulk_wait<SO - 1>();
        __syncthreads();   // all reads of s_in[si] done + out slot free

        // recycle input stage immediately
        if (tid == 0 && k + SI < my_count) {
            long long tn = blockIdx.x + (long long)(k + SI) * gridDim.x;
            uint32_t mb = smem_u32(&s_full[si]);
            mbar_expect_tx(mb, TILE_BYTES);
            bulk_g2s(smem_u32(&s_in[si][0]), x + tn * TILE_ELEMS, TILE_BYTES, mb, pol);
        }

        float4* bout = (float4*)&s_out[so][0];
        bout[tid] = v0;
        bout[tid + TPB] = v1;
        __syncthreads();   // STS visible CTA-wide

        if (tid == 0) {
            fence_async_smem();   // order generic STS before async-proxy read
            bulk_s2g(out + t * TILE_ELEMS, smem_u32(&s_out[so][0]), TILE_BYTES, pol);
            bulk_commit();
        }

        if (++si == SI) { si = 0; ph ^= 1; }
        if (++so == SO) so = 0;
    }

    if (tid == 0 && my_count > 0) bulk_wait<0>();   // drain stores

    // ---- remainder elements (n not multiple of TILE_ELEMS) ----
    if (blockIdx.x == gridDim.x - 1) {
        for (long long i = (long long)ntiles * TILE_ELEMS + tid; i < n; i += TPB)
            out[i] = lcq_elem(__ldcs(&x[i]), c, s_tab, s_lutA);
    }
}

extern "C" void kernel_launch(void* const* d_in, const int* in_sizes, int n_in,
                              void* d_out, int out_size) {
    // metadata order: x, threshold, theta, dst, Qn, Qp, num_elements
    const float* x     = (const float*)d_in[0];
    const float* thr   = (const float*)d_in[1];
    const float* theta = (const float*)d_in[2];
    const float* dst   = (const float*)d_in[3];
    const int*   qp    = (const int*)d_in[5];
    float* out = (float*)d_out;

    int n = in_sizes[0];
    int ntiles = n / TILE_ELEMS;

    int blocks = 148 * 5;               // 5 CTAs/SM (40KB smem each, 200KB/SM)
    if (blocks > ntiles) blocks = ntiles;
    if (blocks < 1) blocks = 1;

    lcq_kernel<<<blocks, TPB>>>(x, thr, theta, dst, qp, out, ntiles, n);
}

// round 12
// speedup vs baseline: 1.0676x; 1.0060x over previous
#include <cuda_runtime.h>
#include <cstdint>

#define KBINS 16
#define MAGIC 8388608.0f      // 2^23
#define TPB 512
#define SI 3                  // input ring stages
#define SO 2                  // output ring stages
#define TILE_ELEMS 4096       // 16KB per tile
#define TILE_BYTES (TILE_ELEMS * 4)
#define RING_BYTES ((SI + SO) * TILE_BYTES)   // 80KB dynamic smem

// ---- mbarrier / bulk-async helpers ----------------------------------------
__device__ __forceinline__ uint32_t smem_u32(const void* p) {
    return (uint32_t)__cvta_generic_to_shared(p);
}
__device__ __forceinline__ void mbar_init(uint32_t a, uint32_t cnt) {
    asm volatile("mbarrier.init.shared.b64 [%0], %1;" :: "r"(a), "r"(cnt) : "memory");
}
__device__ __forceinline__ void mbar_expect_tx(uint32_t a, uint32_t bytes) {
    asm volatile("mbarrier.arrive.expect_tx.shared.b64 _, [%0], %1;"
                 :: "r"(a), "r"(bytes) : "memory");
}
__device__ __forceinline__ void mbar_wait(uint32_t a, uint32_t ph) {
    uint32_t done;
    asm volatile("{\n\t.reg .pred p;\n\t"
                 "mbarrier.try_wait.parity.acquire.cta.shared::cta.b64 p, [%1], %2;\n\t"
                 "selp.b32 %0, 1, 0, p;\n\t}"
                 : "=r"(done) : "r"(a), "r"(ph) : "memory");
    while (!done) {
        asm volatile("{\n\t.reg .pred p;\n\t"
                     "mbarrier.try_wait.parity.acquire.cta.shared::cta.b64 p, [%1], %2, 0x989680;\n\t"
                     "selp.b32 %0, 1, 0, p;\n\t}"
                     : "=r"(done) : "r"(a), "r"(ph) : "memory");
    }
}
__device__ __forceinline__ uint64_t l2_evict_first_policy() {
    uint64_t pol;
    asm("createpolicy.fractional.L2::evict_first.b64 %0, 1.0;" : "=l"(pol));
    return pol;
}
__device__ __forceinline__ void bulk_g2s(uint32_t dst, const void* src,
                                         uint32_t bytes, uint32_t mbar,
                                         uint64_t pol) {
    asm volatile("cp.async.bulk.shared::cluster.global.mbarrier::complete_tx::bytes"
                 ".L2::cache_hint [%0], [%1], %2, [%3], %4;"
                 :: "r"(dst), "l"(src), "r"(bytes), "r"(mbar), "l"(pol) : "memory");
}
__device__ __forceinline__ void bulk_s2g(void* gdst, uint32_t ssrc, uint32_t bytes,
                                         uint64_t pol) {
    asm volatile("cp.async.bulk.global.shared::cta.bulk_group"
                 ".L2::cache_hint [%0], [%1], %2, %3;"
                 :: "l"(gdst), "r"(ssrc), "r"(bytes), "l"(pol) : "memory");
}
__device__ __forceinline__ void bulk_commit() {
    asm volatile("cp.async.bulk.commit_group;" ::: "memory");
}
template <int N>
__device__ __forceinline__ void bulk_wait() {
    asm volatile("cp.async.bulk.wait_group %0;" :: "n"(N) : "memory");
}
__device__ __forceinline__ void fence_async_smem() {
    asm volatile("fence.proxy.async.shared::cta;" ::: "memory");
}

// ---- LCQ per-element math (bit-exact magic-number rounding) ----------------
__device__ __forceinline__ float lcq_elem(float xx, float c,
                                          const float2* __restrict__ tab,
                                          const float* __restrict__ lutA) {
    float f = fminf(fabsf(xx) * c, 15.9999990f);
    int bi = __float_as_int(__fadd_rd(f, MAGIC)) & 15;   // floor(f)
    float2 gd = tab[bi];                                 // {gx, d}
    float y15 = fmaf(gd.x, f, gd.y);
    int q = __float_as_int(__fadd_rn(y15, MAGIC)) & 15;  // rint(y15)
    return copysignf(lutA[q], xx);
}
__device__ __forceinline__ void lcq_vec4(float4& v, float c,
                                         const float2* __restrict__ tab,
                                         const float* __restrict__ lutA) {
    v.x = lcq_elem(v.x, c, tab, lutA);
    v.y = lcq_elem(v.y, c, tab, lutA);
    v.z = lcq_elem(v.z, c, tab, lutA);
    v.w = lcq_elem(v.w, c, tab, lutA);
}

__global__ void __launch_bounds__(TPB)
lcq_kernel(const float* __restrict__ x,
           const float* __restrict__ thr,
           const float* __restrict__ theta,
           const float* __restrict__ dst,
           const int* __restrict__ qp,
           float* __restrict__ out,
           int ntiles, int chunk, int n) {
    extern __shared__ __align__(128) float s_ring[];       // SI+SO tiles
    float* s_in  = s_ring;                                  // SI * TILE_ELEMS
    float* s_out = s_ring + SI * TILE_ELEMS;                // SO * TILE_ELEMS

    __shared__ uint64_t s_full[SI];
    __shared__ float2 s_tab[KBINS];
    __shared__ float  s_lutA[KBINS];
    __shared__ float  s_c;

    const int tid = threadIdx.x;
    const uint64_t pol = l2_evict_first_policy();

    if (tid == 0) {
        // constant tables: softmax/cumsum/affine folds + expand LUT
        float th[KBINS];
        float m = theta[0];
        #pragma unroll
        for (int i = 0; i < KBINS; i++) { th[i] = theta[i]; m = fmaxf(m, th[i]); }
        float sum = 0.0f;
        #pragma unroll
        for (int i = 0; i < KBINS; i++) { th[i] = expf(th[i] - m); sum += th[i]; }
        float inv = 1.0f / sum;
        float gamma[KBINS], beta[KBINS];
        float acc = 0.0f;
        #pragma unroll
        for (int i = 0; i < KBINS; i++) {
            float t = th[i] * inv;
            gamma[i] = t * (float)KBINS;
            beta[i]  = acc;
            acc += t;
        }
        float s = (float)qp[0];
        float alpha = thr[0];
        #pragma unroll
        for (int i = 0; i < KBINS; i++) {
            float gx = s * gamma[i] * 0.0625f;
            s_tab[i] = make_float2(gx, fmaf(-gx, (float)i, s * beta[i]));
        }
        #pragma unroll
        for (int q = 0; q < KBINS; q++) {
            float t = (float)q / s;
            int idx = 0;
            #pragma unroll
            for (int j = 0; j < KBINS; j++)
                if (beta[j] <= t) idx = j;
            s_lutA[q] = alpha * ((t - beta[idx]) / gamma[idx] + dst[idx]);
        }
        s_c = 16.0f / alpha;

        #pragma unroll
        for (int sg = 0; sg < SI; sg++)
            mbar_init(smem_u32(&s_full[sg]), 1);
    }
    __syncthreads();

    const float c = s_c;

    // Contiguous tile range per CTA: [first, first+cnt)
    long long first = (long long)blockIdx.x * chunk;
    int cnt = 0;
    if (first < ntiles) {
        long long rem = ntiles - first;
        cnt = rem < chunk ? (int)rem : chunk;
    }

    // ---- prologue: fill input ring ----
    if (tid == 0) {
        int pre = cnt < SI ? cnt : SI;
        for (int k = 0; k < pre; k++) {
            uint32_t mb = smem_u32(&s_full[k]);
            mbar_expect_tx(mb, TILE_BYTES);
            bulk_g2s(smem_u32(&s_in[k * TILE_ELEMS]),
                     x + (first + k) * TILE_ELEMS, TILE_BYTES, mb, pol);
        }
    }

    // ---- steady state ----
    int si = 0, ph = 0, so = 0;
    for (int k = 0; k < cnt; k++) {
        long long t = first + k;

        mbar_wait(smem_u32(&s_full[si]), ph);

        const float4* bin = (const float4*)&s_in[si * TILE_ELEMS];
        float4 v0 = bin[tid];
        float4 v1 = bin[tid + TPB];
        lcq_vec4(v0, c, s_tab, s_lutA);
        lcq_vec4(v1, c, s_tab, s_lutA);

        // output slot `so` must be free (its S2G from SO iterations ago done)
        if (tid == 0) bulk_wait<SO - 1>();
        __syncthreads();   // all reads of s_in[si] done + out slot free

        // recycle input stage immediately (sequential next tile)
        if (tid == 0 && k + SI < cnt) {
            uint32_t mb = smem_u32(&s_full[si]);
            mbar_expect_tx(mb, TILE_BYTES);
            bulk_g2s(smem_u32(&s_in[si * TILE_ELEMS]),
                     x + (t + SI) * TILE_ELEMS, TILE_BYTES, mb, pol);
        }

        float4* bout = (float4*)&s_out[so * TILE_ELEMS];
        bout[tid] = v0;
        bout[tid + TPB] = v1;
        __syncthreads();   // STS visible CTA-wide

        if (tid == 0) {
            fence_async_smem();   // order generic STS before async-proxy read
            bulk_s2g(out + t * TILE_ELEMS,
                     smem_u32(&s_out[so * TILE_ELEMS]), TILE_BYTES, pol);
            bulk_commit();
        }

        if (++si == SI) { si = 0; ph ^= 1; }
        if (++so == SO) so = 0;
    }

    if (tid == 0 && cnt > 0) bulk_wait<0>();   // drain stores

    // ---- remainder elements (n not multiple of TILE_ELEMS) ----
    if (blockIdx.x == gridDim.x - 1) {
        for (long long i = (long long)ntiles * TILE_ELEMS + tid; i < n; i += TPB)
            out[i] = lcq_elem(__ldcs(&x[i]), c, s_tab, s_lutA);
    }
}

extern "C" void kernel_launch(void* const* d_in, const int* in_sizes, int n_in,
                              void* d_out, int out_size) {
    // metadata order: x, threshold, theta, dst, Qn, Qp, num_elements
    const float* x     = (const float*)d_in[0];
    const float* thr   = (const float*)d_in[1];
    const float* theta = (const float*)d_in[2];
    const float* dst   = (const float*)d_in[3];
    const int*   qp    = (const int*)d_in[5];
    float* out = (float*)d_out;

    int n = in_sizes[0];
    int ntiles = n / TILE_ELEMS;

    int blocks = 148 * 2;               // 2 CTAs/SM (80KB dyn smem each)
    if (blocks > ntiles && ntiles > 0) blocks = ntiles;
    if (blocks < 1) blocks = 1;
    int chunk = (ntiles + blocks - 1) / blocks;
    if (chunk < 1) chunk = 1;

    static int smem_set = 0;  // idempotent attribute set (host-side, capture-safe)
    if (!smem_set) {
        cudaFuncSetAttribute(lcq_kernel,
                             cudaFuncAttributeMaxDynamicSharedMemorySize,
                             RING_BYTES);
        smem_set = 1;
    }

    lcq_kernel<<<blocks, TPB, RING_BYTES>>>(x, thr, theta, dst, qp, out,
                                            ntiles, chunk, n);
}